// round 15
// baseline (speedup 1.0000x reference)
#include <cuda_runtime.h>
#include <cuda_fp16.h>
#include <math.h>
#include <stdint.h>

#define Bv 4
#define Lv 8192
#define Dm 1024
#define Hh 16
#define DKv 64
#define Uv 50
#define BLv (Bv*Lv)            // 32768
#define SPLIT 8
#define LSPL (Lv/SPLIT)        // 1024
#define TK 32

// ---------------- scratch (device globals; no allocations allowed) ----------
#define XS_CELLS ((size_t)2048*64*32)
__device__ float g_Q[BLv*Dm];          // 128 MB
__device__ float g_K[BLv*Dm];          // 128 MB
__device__ float g_V[BLv*Dm];          // 128 MB
__device__ uint32_t g_XS[XS_CELLS*8];             // 128 MB: X limbs, hi plane then lo plane
__device__ uint32_t g_WS[(size_t)3*128*64*32*4];  // 12 MB: W limbs (x32), frag order
__device__ float g_M[Bv*Hh*Lv];
__device__ int   g_top[Bv*Hh*Uv];
__device__ float g_pm[Bv*Hh*SPLIT*Uv];
__device__ float g_pl[Bv*Hh*SPLIT*Uv];
__device__ float g_pctx[Bv*Hh*SPLIT*Uv*DKv];
__device__ float g_ctx[Bv*Hh*Uv*DKv];
__device__ float g_vsum[Bv*Dm];
__device__ float g_base[Bv*Dm];

// ---------------- helpers ----------------------------------------------------
__device__ __forceinline__ uint32_t packsplit(float x, float y, uint32_t &lo){
    __half hx = __float2half_rn(x);
    __half hy = __float2half_rn(y);
    __half lx = __float2half_rn(x - __half2float(hx));
    __half ly = __float2half_rn(y - __half2float(hy));
    __half2 h2 = __halves2half2(hx, hy);
    __half2 l2 = __halves2half2(lx, ly);
    lo = *reinterpret_cast<uint32_t*>(&l2);
    return *reinterpret_cast<uint32_t*>(&h2);
}

__device__ __forceinline__ void mma16(float* c, const uint32_t* a, const uint32_t* b){
    asm volatile(
        "mma.sync.aligned.m16n8k16.row.col.f32.f16.f16.f32 "
        "{%0,%1,%2,%3}, {%4,%5,%6,%7}, {%8,%9}, {%0,%1,%2,%3};"
        : "+f"(c[0]), "+f"(c[1]), "+f"(c[2]), "+f"(c[3])
        : "r"(a[0]), "r"(a[1]), "r"(a[2]), "r"(a[3]), "r"(b[0]), "r"(b[1]));
}

__device__ __forceinline__ uint32_t sm_u32(const void* p){
    uint32_t a;
    asm("{ .reg .u64 t; cvta.to.shared.u64 t, %1; cvt.u32.u64 %0, t; }"
        : "=r"(a) : "l"(p));
    return a;
}

__device__ __forceinline__ void cpasync16(uint32_t dst, const void* src){
    asm volatile("cp.async.cg.shared.global [%0], [%1], 16;"
                 :: "r"(dst), "l"(src) : "memory");
}
#define CP_COMMIT() asm volatile("cp.async.commit_group;" ::: "memory")
#define CP_WAIT1()  asm volatile("cp.async.wait_group 1;" ::: "memory")

// ---------------- kernel A: split X into limb planes (frag order) -----------
__global__ __launch_bounds__(256) void split_x_kernel(const float* __restrict__ X){
    const int id = blockIdx.x*256 + threadIdx.x;
    const int mb   = id >> 11;
    const int c    = (id >> 5) & 63;
    const int lane = id & 31;
    const int r0 = mb*16 + (lane >> 2);
    const int k0 = c*16 + 2*(lane & 3);
    const float* p0 = X + (size_t)r0*Dm + k0;
    float2 a00 = *reinterpret_cast<const float2*>(p0);
    float2 a10 = *reinterpret_cast<const float2*>(p0 + 8*Dm);
    float2 a01 = *reinterpret_cast<const float2*>(p0 + 8);
    float2 a11 = *reinterpret_cast<const float2*>(p0 + 8*Dm + 8);
    uint32_t h0,h1,h2,h3, l0,l1,l2,l3;
    h0 = packsplit(a00.x, a00.y, l0);
    h1 = packsplit(a10.x, a10.y, l1);
    h2 = packsplit(a01.x, a01.y, l2);
    h3 = packsplit(a11.x, a11.y, l3);
    *reinterpret_cast<uint4*>(&g_XS[(size_t)id*4])              = make_uint4(h0,h1,h2,h3);
    *reinterpret_cast<uint4*>(&g_XS[XS_CELLS*4 + (size_t)id*4]) = make_uint4(l0,l1,l2,l3);
}

// ---------------- kernel B: split W (x32) into limbs; also zero vsum ---------
__global__ __launch_bounds__(256) void split_w_kernel(
    const float* __restrict__ Wq, const float* __restrict__ Wk,
    const float* __restrict__ Wv)
{
    if (blockIdx.x < 16) g_vsum[blockIdx.x*256 + threadIdx.x] = 0.0f;

    const int id = blockIdx.x*256 + threadIdx.x;
    const int gemm = id >> 18;
    const int rem  = id & 262143;
    const int nb   = rem >> 11;
    const int c    = (rem >> 5) & 63;
    const int lane = rem & 31;
    const float* W = (gemm == 0) ? Wq : (gemm == 1) ? Wk : Wv;
    const int row = nb*8 + (lane >> 2);
    const int k0  = c*16 + 2*(lane & 3);
    const float* p = W + (size_t)row*Dm + k0;
    float2 b0 = *reinterpret_cast<const float2*>(p);
    float2 b1 = *reinterpret_cast<const float2*>(p + 8);
    uint32_t bh0, bh1, bl0, bl1;
    bh0 = packsplit(b0.x*32.f, b0.y*32.f, bl0);
    bh1 = packsplit(b1.x*32.f, b1.y*32.f, bl1);
    reinterpret_cast<uint4*>(&g_WS[(size_t)id*4])[0] = make_uint4(bh0,bh1,bl0,bl1);
}

// ======================= kernel 1: QKV GEMM ===================================
// Q,K: 3-limb split; V: 2-limb (drops alo.bhi — V errors don't feed top-k,
// and the broadcast mean averages them out; ~7.5e-5 global rel err).
__global__ __launch_bounds__(256,2) void qkv_f16_kernel(
    const float* __restrict__ bq, const float* __restrict__ bk,
    const float* __restrict__ bv)
{
    const int gemm = blockIdx.z;
    const float* bias = (gemm == 0) ? bq : (gemm == 1) ? bk : bv;
    float* out = (gemm == 0) ? g_Q : (gemm == 1) ? g_K : g_V;
    const bool full3 = (gemm != 2);

    const int n0 = blockIdx.x * 128;
    const int m0 = blockIdx.y * 128;

    extern __shared__ uint32_t smq[];
    const uint32_t smb = sm_u32(smq);

    const int t = threadIdx.x;
    const int lane = t & 31;
    const int wid  = t >> 5;
    const int warp_m = wid & 3;
    const int warp_n = wid >> 2;

    const int fA = wid, lA = lane;
    const char* srcAh = (const char*)g_XS
        + ((size_t)((blockIdx.y*8 + fA)*64)*32 + lA)*16;
    const char* srcAl = srcAh + XS_CELLS*16;
    const char* srcB1 = (const char*)g_WS
        + ((size_t)((gemm*128 + blockIdx.x*16 + fA)*64)*32 + lA)*16;
    const char* srcB2 = srcB1 + (size_t)8*64*32*16;
    const uint32_t dAh = (fA*32 + lA)*16;
    const uint32_t dAl = dAh + 4096;
    const uint32_t dB1 = 8192 + (fA*32 + lA)*16;
    const uint32_t dB2 = dB1 + 4096;

    float acc[2][8][4];
    #pragma unroll
    for (int i = 0; i < 2; ++i)
        #pragma unroll
        for (int j = 0; j < 8; ++j)
            #pragma unroll
            for (int r = 0; r < 4; ++r) acc[i][j][r] = 0.0f;

    #pragma unroll
    for (int p = 0; p < 2; ++p) {
        const uint32_t b = smb + p*16384;
        cpasync16(b + dAh, srcAh + (size_t)p*512);
        cpasync16(b + dAl, srcAl + (size_t)p*512);
        cpasync16(b + dB1, srcB1 + (size_t)p*512);
        cpasync16(b + dB2, srcB2 + (size_t)p*512);
        CP_COMMIT();
    }

    #pragma unroll 1
    for (int c = 0; c < 64; ++c) {
        CP_WAIT1();
        __syncthreads();

        if (c + 2 < 64) {
            const uint32_t b = smb + ((c+2) & 3)*16384;
            cpasync16(b + dAh, srcAh + (size_t)(c+2)*512);
            cpasync16(b + dAl, srcAl + (size_t)(c+2)*512);
            cpasync16(b + dB1, srcB1 + (size_t)(c+2)*512);
            cpasync16(b + dB2, srcB2 + (size_t)(c+2)*512);
        }
        CP_COMMIT();

        const uint32_t* C = smq + (c & 3)*4096;
        uint32_t ah[2][4], al[2][4];
        #pragma unroll
        for (int im = 0; im < 2; ++im) {
            const int base = ((warp_m*2 + im)*32 + lane)*4;
            *reinterpret_cast<uint4*>(ah[im]) = *reinterpret_cast<const uint4*>(&C[base]);
            *reinterpret_cast<uint4*>(al[im]) = *reinterpret_cast<const uint4*>(&C[base + 1024]);
        }
        #pragma unroll
        for (int in = 0; in < 8; ++in) {
            const int base = 2048 + ((warp_n*8 + in)*32 + lane)*4;
            uint4 q = *reinterpret_cast<const uint4*>(&C[base]);
            uint32_t bh[2] = {q.x, q.y};
            uint32_t bl[2] = {q.z, q.w};
            #pragma unroll
            for (int im = 0; im < 2; ++im) {
                if (full3) mma16(acc[im][in], al[im], bh);
                mma16(acc[im][in], ah[im], bl);
                mma16(acc[im][in], ah[im], bh);
            }
        }
    }

    const float inv32 = 0.03125f;
    #pragma unroll
    for (int im = 0; im < 2; ++im) {
        const int m = m0 + warp_m*32 + im*16 + (lane >> 2);
        #pragma unroll
        for (int in = 0; in < 8; ++in) {
            const int n = n0 + warp_n*64 + in*8 + (lane & 3)*2;
            const float b0 = __ldg(&bias[n]);
            const float b1 = __ldg(&bias[n+1]);
            float2 v0 = make_float2(acc[im][in][0]*inv32 + b0, acc[im][in][1]*inv32 + b1);
            float2 v1 = make_float2(acc[im][in][2]*inv32 + b0, acc[im][in][3]*inv32 + b1);
            *reinterpret_cast<float2*>(&out[(size_t)m*Dm + n])     = v0;
            *reinterpret_cast<float2*>(&out[(size_t)(m+8)*Dm + n]) = v1;
        }
    }
}

// ---------------- kernel 2: sparsity measure M via tensor cores --------------
__global__ __launch_bounds__(256) void m_tc_kernel(const int* __restrict__ idx_k){
    const int b = blockIdx.z, h = blockIdx.y;
    const int l0 = blockIdx.x * 128;

    __shared__ uint32_t Ah[8][4][32][4];
    __shared__ uint32_t Al[8][4][32][4];
    __shared__ uint32_t Bs[7][4][32][4];

    const int t = threadIdx.x;
    const int lane = t & 31;
    const int w = t >> 5;

    #pragma unroll
    for (int i = 0; i < 4; ++i) {
        const int id = t + i*256;
        const int frag = id >> 7, ln = (id >> 2) & 31, ch = id & 3;
        const int r0 = l0 + frag*16 + (ln >> 2);
        const int c0 = ch*16 + 2*(ln & 3);
        const float* q0 = &g_Q[(size_t)(b*Lv + r0)*Dm + h*DKv + c0];
        const float* q1 = q0 + 8*Dm;
        float2 x00 = *reinterpret_cast<const float2*>(q0);
        float2 x10 = *reinterpret_cast<const float2*>(q1);
        float2 x01 = *reinterpret_cast<const float2*>(q0 + 8);
        float2 x11 = *reinterpret_cast<const float2*>(q1 + 8);
        uint32_t h0,h1,h2,h3, e0,e1,e2,e3;
        h0 = packsplit(x00.x, x00.y, e0);
        h1 = packsplit(x10.x, x10.y, e1);
        h2 = packsplit(x01.x, x01.y, e2);
        h3 = packsplit(x11.x, x11.y, e3);
        *reinterpret_cast<uint4*>(&Ah[frag][ch][ln][0]) = make_uint4(h0,h1,h2,h3);
        *reinterpret_cast<uint4*>(&Al[frag][ch][ln][0]) = make_uint4(e0,e1,e2,e3);
    }
    #pragma unroll
    for (int i = 0; i < 4; ++i) {
        const int id = t + i*256;
        if (id < 896) {
            const int frag = id >> 7, ln = (id >> 2) & 31, ch = id & 3;
            const int n = frag*8 + (ln >> 2);
            uint32_t bh0=0, bh1=0, bl0=0, bl1=0;
            if (n < Uv) {
                const int row = __ldg(&idx_k[n]);
                const int c0 = ch*16 + 2*(ln & 3);
                const float* kp = &g_K[(size_t)(b*Lv + row)*Dm + h*DKv + c0];
                float2 y0 = *reinterpret_cast<const float2*>(kp);
                float2 y1 = *reinterpret_cast<const float2*>(kp + 8);
                bh0 = packsplit(y0.x, y0.y, bl0);
                bh1 = packsplit(y1.x, y1.y, bl1);
            }
            *reinterpret_cast<uint4*>(&Bs[frag][ch][ln][0]) = make_uint4(bh0,bh1,bl0,bl1);
        }
    }
    __syncthreads();

    float acc[7][4];
    #pragma unroll
    for (int in = 0; in < 7; ++in)
        #pragma unroll
        for (int r = 0; r < 4; ++r) acc[in][r] = 0.0f;

    #pragma unroll
    for (int ch = 0; ch < 4; ++ch) {
        uint32_t ahr[4], alr[4];
        *reinterpret_cast<uint4*>(ahr) = *reinterpret_cast<const uint4*>(&Ah[w][ch][lane][0]);
        *reinterpret_cast<uint4*>(alr) = *reinterpret_cast<const uint4*>(&Al[w][ch][lane][0]);
        #pragma unroll
        for (int in = 0; in < 7; ++in) {
            uint4 q = *reinterpret_cast<const uint4*>(&Bs[in][ch][lane][0]);
            uint32_t bh[2] = {q.x, q.y};
            uint32_t bl[2] = {q.z, q.w};
            mma16(acc[in], alr, bh);
            mma16(acc[in], ahr, bl);
            mma16(acc[in], ahr, bh);
        }
    }

    const int colbase = (lane & 3)*2;
    float mx0 = -1e30f, sm0 = 0.f, mx1 = -1e30f, sm1 = 0.f;
    #pragma unroll
    for (int in = 0; in < 7; ++in) {
        const int c0 = in*8 + colbase;
        if (c0 < Uv) {
            mx0 = fmaxf(mx0, acc[in][0]); sm0 += acc[in][0];
            mx1 = fmaxf(mx1, acc[in][2]); sm1 += acc[in][2];
        }
        if (c0 + 1 < Uv) {
            mx0 = fmaxf(mx0, acc[in][1]); sm0 += acc[in][1];
            mx1 = fmaxf(mx1, acc[in][3]); sm1 += acc[in][3];
        }
    }
    #pragma unroll
    for (int o = 1; o < 4; o <<= 1) {
        mx0 = fmaxf(mx0, __shfl_xor_sync(0xffffffffu, mx0, o));
        sm0 += __shfl_xor_sync(0xffffffffu, sm0, o);
        mx1 = fmaxf(mx1, __shfl_xor_sync(0xffffffffu, mx1, o));
        sm1 += __shfl_xor_sync(0xffffffffu, sm1, o);
    }
    if ((lane & 3) == 0) {
        const int r = l0 + w*16 + (lane >> 2);
        float* Mrow = &g_M[(size_t)(b*Hh + h)*Lv + r];
        Mrow[0] = mx0 - sm0*(1.0f/Uv);
        Mrow[8] = mx1 - sm1*(1.0f/Uv);
    }
}

// ---------------- kernel 3: top-k (k=50 of 8192) per (b,h) -------------------
__global__ __launch_bounds__(512) void topk_kernel(){
    const int bh = blockIdx.x;
    __shared__ float vals[Lv];
    __shared__ float rv[512];
    __shared__ int   ri[512];
    const int t = threadIdx.x;

    for (int i = t; i < Lv; i += 512) vals[i] = g_M[(size_t)bh*Lv + i];
    __syncthreads();

    for (int it = 0; it < Uv; ++it) {
        float best = -1e30f; int bi = Lv;
        for (int i = t; i < Lv; i += 512) {
            float v = vals[i];
            if (v > best || (v == best && i < bi)) { best = v; bi = i; }
        }
        rv[t] = best; ri[t] = bi;
        __syncthreads();
        for (int s = 256; s > 0; s >>= 1) {
            if (t < s) {
                if (rv[t+s] > rv[t] || (rv[t+s] == rv[t] && ri[t+s] < ri[t])) {
                    rv[t] = rv[t+s]; ri[t] = ri[t+s];
                }
            }
            __syncthreads();
        }
        if (t == 0) { g_top[bh*Uv + it] = ri[0]; vals[ri[0]] = -1e30f; }
        __syncthreads();
    }
}

// ---------------- kernel 4: V column sums (for mean) -------------------------
__global__ void vsum_kernel(){
    const int b = blockIdx.z;
    const int d = blockIdx.x*128 + threadIdx.x;
    const int c = blockIdx.y;
    float s = 0.0f;
    const int lbeg = c*256, lend = lbeg + 256;
    for (int l = lbeg; l < lend; ++l) s += g_V[(size_t)(b*Lv + l)*Dm + d];
    atomicAdd(&g_vsum[b*Dm + d], s);
}

// ---------------- kernel 5: flash attention (tensor-core QK^T and PV) --------
__global__ __launch_bounds__(512) void attn_partial_kernel(){
    extern __shared__ float sma[];
    const int bh = blockIdx.x;
    const int sp = blockIdx.y;
    const int b = bh / Hh, h = bh % Hh;
    const int t = threadIdx.x;
    const int lane = t & 31;
    const int w = t >> 5;

    float* Qraw = sma;
    float* Ps   = sma + 4096;
    float* m_s  = sma + 6400;
    float* l_s  = sma + 6464;
    float* c_s  = sma + 6528;
    uint32_t* Qh = reinterpret_cast<uint32_t*>(sma + 15296);
    uint32_t* Ql = Qh + 2048;
    uint32_t* Kl = Ql + 2048;
    uint32_t* Vl = Kl + 2048;
    const uint32_t smab = sm_u32(sma);

    for (int i = t; i < 64*64; i += 512) {
        const int q = i >> 6, d = i & 63;
        float v = 0.0f;
        if (q < Uv) {
            const int l = g_top[bh*Uv + q];
            v = g_Q[(size_t)(b*Lv + l)*Dm + h*DKv + d];
        }
        Qraw[i] = v;
    }
    if (t < Uv) { m_s[t] = -1e30f; l_s[t] = 0.0f; }
    if (t < 64) c_s[t] = 1.0f;
    __syncthreads();

    {
        const int mf = t >> 7, ch = (t >> 5) & 3, ln = t & 31;
        const int r0 = mf*16 + (ln >> 2), k0 = ch*16 + 2*(ln & 3);
        float2 x00 = *reinterpret_cast<const float2*>(&Qraw[r0*64 + k0]);
        float2 x10 = *reinterpret_cast<const float2*>(&Qraw[(r0+8)*64 + k0]);
        float2 x01 = *reinterpret_cast<const float2*>(&Qraw[r0*64 + k0 + 8]);
        float2 x11 = *reinterpret_cast<const float2*>(&Qraw[(r0+8)*64 + k0 + 8]);
        uint32_t h0,h1,h2,h3, e0,e1,e2,e3;
        h0 = packsplit(x00.x, x00.y, e0);
        h1 = packsplit(x10.x, x10.y, e1);
        h2 = packsplit(x01.x, x01.y, e2);
        h3 = packsplit(x11.x, x11.y, e3);
        const int cell = ((mf*4 + ch)*32 + ln)*4;
        *reinterpret_cast<uint4*>(&Qh[cell]) = make_uint4(h0,h1,h2,h3);
        *reinterpret_cast<uint4*>(&Ql[cell]) = make_uint4(e0,e1,e2,e3);
    }

    const int ldrow = t >> 4;
    const int lddq  = t & 15;
    const uint32_t kdst = smab + (6592 + ldrow*68 + lddq*4)*4;
    const uint32_t vdst = kdst + 2176*4;

    {
        size_t g = (size_t)(b*Lv + sp*LSPL + ldrow)*Dm + h*DKv + lddq*4;
        cpasync16(kdst, &g_K[g]);
        cpasync16(vdst, &g_V[g]);
    }
    CP_COMMIT();

    float o[2][4];
    #pragma unroll
    for (int j = 0; j < 2; ++j)
        #pragma unroll
        for (int r = 0; r < 4; ++r) o[j][r] = 0.0f;

    const int mf  = w >> 2;
    const int nfS = w & 3;
    const int nf0 = (w & 3)*2;

    const int NT = LSPL/TK;   // 32
    #pragma unroll 1
    for (int i = 0; i < NT; ++i) {
        __syncthreads();
        if (i + 1 < NT) {
            const uint32_t off = ((i+1) & 1)*4352*4;
            size_t g = (size_t)(b*Lv + sp*LSPL + (i+1)*TK + ldrow)*Dm + h*DKv + lddq*4;
            cpasync16(kdst + off, &g_K[g]);
            cpasync16(vdst + off, &g_V[g]);
        }
        CP_COMMIT();
        CP_WAIT1();
        __syncthreads();

        const float* Kr = sma + 6592 + (i & 1)*4352;
        const float* Vr = Kr + 2176;

        {
            const int nf = t >> 7, ch = (t >> 5) & 3, ln = t & 31;
            const int n = nf*8 + (ln >> 2), k0 = ch*16 + 2*(ln & 3);
            float2 y0 = *reinterpret_cast<const float2*>(&Kr[n*68 + k0]);
            float2 y1 = *reinterpret_cast<const float2*>(&Kr[n*68 + k0 + 8]);
            uint32_t bh0, bh1, bl0, bl1;
            bh0 = packsplit(y0.x, y0.y, bl0);
            bh1 = packsplit(y1.x, y1.y, bl1);
            *reinterpret_cast<uint4*>(&Kl[((nf*4+ch)*32+ln)*4]) = make_uint4(bh0,bh1,bl0,bl1);
        }
        {
            const int nf = t >> 6, ch = (t >> 5) & 1, ln = t & 31;
            const int n = nf*8 + (ln >> 2), k0 = ch*16 + 2*(ln & 3);
            float v00 = Vr[k0*68 + n],     v01 = Vr[(k0+1)*68 + n];
            float v10 = Vr[(k0+8)*68 + n], v11 = Vr[(k0+9)*68 + n];
            uint32_t bh0, bh1, bl0, bl1;
            bh0 = packsplit(v00, v01, bl0);
            bh1 = packsplit(v10, v11, bl1);
            *reinterpret_cast<uint4*>(&Vl[((nf*2+ch)*32+ln)*4]) = make_uint4(bh0,bh1,bl0,bl1);
        }
        __syncthreads();

        {
            float s[4] = {0.f, 0.f, 0.f, 0.f};
            #pragma unroll
            for (int ch = 0; ch < 4; ++ch) {
                uint32_t ah[4], al[4];
                *reinterpret_cast<uint4*>(ah) = *reinterpret_cast<const uint4*>(&Qh[((mf*4+ch)*32+lane)*4]);
                *reinterpret_cast<uint4*>(al) = *reinterpret_cast<const uint4*>(&Ql[((mf*4+ch)*32+lane)*4]);
                uint4 q4 = *reinterpret_cast<const uint4*>(&Kl[((nfS*4+ch)*32+lane)*4]);
                uint32_t bh2[2] = {q4.x, q4.y};
                uint32_t bl2[2] = {q4.z, q4.w};
                mma16(s, al, bh2);
                mma16(s, ah, bl2);
                mma16(s, ah, bh2);
            }
            const int q0 = mf*16 + (lane >> 2);
            const int col = nfS*8 + (lane & 3)*2;
            *reinterpret_cast<float2*>(&Ps[q0*36 + col])     = make_float2(s[0]*0.125f, s[1]*0.125f);
            *reinterpret_cast<float2*>(&Ps[(q0+8)*36 + col]) = make_float2(s[2]*0.125f, s[3]*0.125f);
        }
        __syncthreads();

        {
            const int q = (t < 400) ? (t >> 3) : 49;
            const int g = t & 7;
            float4 p4 = *reinterpret_cast<const float4*>(&Ps[q*36 + g*4]);
            float lm = fmaxf(fmaxf(p4.x, p4.y), fmaxf(p4.z, p4.w));
            #pragma unroll
            for (int oo = 1; oo < 8; oo <<= 1)
                lm = fmaxf(lm, __shfl_xor_sync(0xffffffffu, lm, oo, 8));
            const float mold = m_s[q];
            const float nm = fmaxf(mold, lm);
            p4.x = __expf(p4.x - nm);
            p4.y = __expf(p4.y - nm);
            p4.z = __expf(p4.z - nm);
            p4.w = __expf(p4.w - nm);
            float lsum = p4.x + p4.y + p4.z + p4.w;
            #pragma unroll
            for (int oo = 1; oo < 8; oo <<= 1)
                lsum += __shfl_xor_sync(0xffffffffu, lsum, oo, 8);
            if (t < 400) {
                *reinterpret_cast<float4*>(&Ps[q*36 + g*4]) = p4;
                if (g == 0) {
                    float cc = __expf(mold - nm);
                    c_s[q] = cc;
                    l_s[q] = l_s[q]*cc + lsum;
                    m_s[q] = nm;
                }
            }
        }
        __syncthreads();

        {
            const int ro = mf*16 + (lane >> 2);
            const float c0 = c_s[ro], c1 = c_s[ro + 8];
            #pragma unroll
            for (int j = 0; j < 2; ++j) {
                o[j][0] *= c0; o[j][1] *= c0;
                o[j][2] *= c1; o[j][3] *= c1;
            }
            #pragma unroll
            for (int ch = 0; ch < 2; ++ch) {
                const int k0 = ch*16 + 2*(lane & 3);
                float2 p00 = *reinterpret_cast<const float2*>(&Ps[ro*36 + k0]);
                float2 p10 = *reinterpret_cast<const float2*>(&Ps[(ro+8)*36 + k0]);
                float2 p01 = *reinterpret_cast<const float2*>(&Ps[ro*36 + k0 + 8]);
                float2 p11 = *reinterpret_cast<const float2*>(&Ps[(ro+8)*36 + k0 + 8]);
                uint32_t ah[4], al[4];
                ah[0] = packsplit(p00.x, p00.y, al[0]);
                ah[1] = packsplit(p10.x, p10.y, al[1]);
                ah[2] = packsplit(p01.x, p01.y, al[2]);
                ah[3] = packsplit(p11.x, p11.y, al[3]);
                #pragma unroll
                for (int j = 0; j < 2; ++j) {
                    uint4 q4 = *reinterpret_cast<const uint4*>(&Vl[(((nf0+j)*2+ch)*32+lane)*4]);
                    uint32_t bh2[2] = {q4.x, q4.y};
                    uint32_t bl2[2] = {q4.z, q4.w};
                    mma16(o[j], al, bh2);
                    mma16(o[j], ah, bl2);
                    mma16(o[j], ah, bh2);
                }
            }
        }
    }

    {
        const int ro = mf*16 + (lane >> 2);
        #pragma unroll
        for (int j = 0; j < 2; ++j) {
            const int d = (nf0+j)*8 + (lane & 3)*2;
            if (ro < Uv)
                *reinterpret_cast<float2*>(&g_pctx[(size_t)((bh*SPLIT+sp)*Uv + ro)*DKv + d])
                    = make_float2(o[j][0], o[j][1]);
            if (ro + 8 < Uv)
                *reinterpret_cast<float2*>(&g_pctx[(size_t)((bh*SPLIT+sp)*Uv + ro + 8)*DKv + d])
                    = make_float2(o[j][2], o[j][3]);
        }
    }
    if (t < Uv) {
        g_pm[(bh*SPLIT + sp)*Uv + t] = m_s[t];
        g_pl[(bh*SPLIT + sp)*Uv + t] = l_s[t];
    }
}

// ---------------- kernel 6: combine split partials ---------------------------
__global__ __launch_bounds__(64) void attn_combine_kernel(){
    const int i = blockIdx.x;
    const int q = i % Uv, bh = i / Uv;
    __shared__ float w[SPLIT];
    __shared__ float inv;
    if (threadIdx.x == 0) {
        float M = -1e30f;
        for (int s = 0; s < SPLIT; ++s) M = fmaxf(M, g_pm[(bh*SPLIT+s)*Uv + q]);
        float tot = 0.f;
        for (int s = 0; s < SPLIT; ++s) {
            float e = __expf(g_pm[(bh*SPLIT+s)*Uv + q] - M);
            w[s] = e;
            tot += g_pl[(bh*SPLIT+s)*Uv + q] * e;
        }
        inv = 1.0f / tot;
    }
    __syncthreads();
    const int d = threadIdx.x;
    float c = 0.f;
    for (int s = 0; s < SPLIT; ++s)
        c += g_pctx[(size_t)((bh*SPLIT+s)*Uv + q)*DKv + d] * w[s];
    g_ctx[(size_t)i*DKv + d] = c * inv;
}

// ---------------- kernel 7: base output row per batch ------------------------
__global__ __launch_bounds__(256) void base_kernel(const float* __restrict__ Wo,
                                                   const float* __restrict__ bo){
    const int b = blockIdx.y;
    const int warp = threadIdx.x >> 5, lane = threadIdx.x & 31;
    const int j = blockIdx.x*8 + warp;
    float s = 0.f;
    for (int d0 = lane; d0 < Dm; d0 += 32)
        s += g_vsum[b*Dm + d0] * Wo[(size_t)j*Dm + d0];
    #pragma unroll
    for (int o = 16; o; o >>= 1) s += __shfl_down_sync(0xffffffffu, s, o);
    if (lane == 0) g_base[b*Dm + j] = s*(1.0f/Lv) + bo[j];
}

// ---------------- kernel 8: broadcast base rows into output -------------------
__global__ void fill_kernel(float* __restrict__ out){
    const int i = blockIdx.x*blockDim.x + threadIdx.x;
    const int b  = i >> 21;
    const int j4 = i & 255;
    float4 v = *reinterpret_cast<const float4*>(&g_base[b*Dm + j4*4]);
    reinterpret_cast<float4*>(out)[i] = v;
}

// ---------------- kernel 9: rank-64 corrections (Wo read once per block) -----
__global__ __launch_bounds__(256) void corr_kernel(const float* __restrict__ Wo,
                                                   float* __restrict__ out){
    const int bh = blockIdx.y;
    const int b = bh / Hh, h = bh % Hh;
    const int j = blockIdx.x*256 + threadIdx.x;
    const int t = threadIdx.x;

    __shared__ float delta[Uv][DKv];
    __shared__ int   ls[Uv];

    if (t < Uv) ls[t] = g_top[bh*Uv + t];
    for (int i = t; i < Uv*DKv; i += 256) {
        const int u = i >> 6, dd = i & 63;
        delta[u][dd] = g_ctx[(size_t)(bh*Uv + u)*DKv + dd]
                     - g_vsum[b*Dm + h*DKv + dd]*(1.0f/Lv);
    }
    __syncthreads();

    float4 w[16];
    const float4* wr = reinterpret_cast<const float4*>(Wo + (size_t)j*Dm + h*DKv);
    #pragma unroll
    for (int dd = 0; dd < 16; ++dd) w[dd] = wr[dd];

    #pragma unroll 2
    for (int u = 0; u < Uv; ++u) {
        float s = 0.f;
        #pragma unroll
        for (int dd = 0; dd < 16; ++dd) {
            s += delta[u][dd*4+0]*w[dd].x + delta[u][dd*4+1]*w[dd].y
               + delta[u][dd*4+2]*w[dd].z + delta[u][dd*4+3]*w[dd].w;
        }
        atomicAdd(&out[(size_t)(b*Lv + ls[u])*Dm + j], s);
    }
}

// ---------------- launch ------------------------------------------------------
extern "C" void kernel_launch(void* const* d_in, const int* in_sizes, int n_in,
                              void* d_out, int out_size)
{
    const float* x    = (const float*)d_in[0];
    const float* Wq   = (const float*)d_in[1];
    const float* bq   = (const float*)d_in[2];
    const float* Wk   = (const float*)d_in[3];
    const float* bk   = (const float*)d_in[4];
    const float* Wv   = (const float*)d_in[5];
    const float* bv   = (const float*)d_in[6];
    const float* Wo   = (const float*)d_in[7];
    const float* bo   = (const float*)d_in[8];
    const int*   idxk = (const int*)d_in[9];
    float* out = (float*)d_out;

    cudaFuncSetAttribute(qkv_f16_kernel,
                         cudaFuncAttributeMaxDynamicSharedMemorySize, 65536);
    cudaFuncSetAttribute(attn_partial_kernel,
                         cudaFuncAttributeMaxDynamicSharedMemorySize, 94208);

    split_x_kernel<<<(2048*64*32)/256, 256>>>(x);
    split_w_kernel<<<(3*128*64*32)/256, 256>>>(Wq, Wk, Wv);
    qkv_f16_kernel<<<dim3(Dm/128, BLv/128, 3), 256, 65536>>>(bq, bk, bv);
    m_tc_kernel<<<dim3(Lv/128, Hh, Bv), 256>>>(idxk);
    vsum_kernel<<<dim3(Dm/128, Lv/256, Bv), 128>>>();
    topk_kernel<<<Bv*Hh, 512>>>();
    attn_partial_kernel<<<dim3(Bv*Hh, SPLIT), 512, 94208>>>();
    attn_combine_kernel<<<Bv*Hh*Uv, 64>>>();
    base_kernel<<<dim3(Dm/8, Bv), 256>>>(Wo, bo);
    fill_kernel<<<(BLv*Dm/4)/256, 256>>>(out);
    corr_kernel<<<dim3(4, Bv*Hh), 256>>>(Wo, out);
}

// round 16
// speedup vs baseline: 1.1279x; 1.1279x over previous
#include <cuda_runtime.h>
#include <cuda_fp16.h>
#include <math.h>
#include <stdint.h>

#define Bv 4
#define Lv 8192
#define Dm 1024
#define Hh 16
#define DKv 64
#define Uv 50
#define BLv (Bv*Lv)            // 32768
#define SPLIT 8
#define LSPL (Lv/SPLIT)        // 1024
#define TK 32

// ---------------- scratch (device globals; no allocations allowed) ----------
#define XS_CELLS ((size_t)2048*64*32)
__device__ float g_Q[BLv*Dm];          // 128 MB
__device__ float g_K[BLv*Dm];          // 128 MB
__device__ float g_V[BLv*Dm];          // 128 MB
__device__ uint32_t g_XS[XS_CELLS*8];             // 128 MB: X limbs, hi plane then lo plane
__device__ uint32_t g_WS[(size_t)3*128*64*32*4];  // 12 MB: W limbs (x32), frag order
__device__ float g_M[Bv*Hh*Lv];
__device__ int   g_top[Bv*Hh*Uv];
__device__ float g_pm[Bv*Hh*SPLIT*Uv];
__device__ float g_pl[Bv*Hh*SPLIT*Uv];
__device__ float g_pctx[Bv*Hh*SPLIT*Uv*DKv];
__device__ float g_ctx[Bv*Hh*Uv*DKv];
__device__ float g_vsum[Bv*Dm];
__device__ float g_base[Bv*Dm];

// ---------------- helpers ----------------------------------------------------
__device__ __forceinline__ uint32_t packsplit(float x, float y, uint32_t &lo){
    __half hx = __float2half_rn(x);
    __half hy = __float2half_rn(y);
    __half lx = __float2half_rn(x - __half2float(hx));
    __half ly = __float2half_rn(y - __half2float(hy));
    __half2 h2 = __halves2half2(hx, hy);
    __half2 l2 = __halves2half2(lx, ly);
    lo = *reinterpret_cast<uint32_t*>(&l2);
    return *reinterpret_cast<uint32_t*>(&h2);
}

__device__ __forceinline__ void mma16(float* c, const uint32_t* a, const uint32_t* b){
    asm volatile(
        "mma.sync.aligned.m16n8k16.row.col.f32.f16.f16.f32 "
        "{%0,%1,%2,%3}, {%4,%5,%6,%7}, {%8,%9}, {%0,%1,%2,%3};"
        : "+f"(c[0]), "+f"(c[1]), "+f"(c[2]), "+f"(c[3])
        : "r"(a[0]), "r"(a[1]), "r"(a[2]), "r"(a[3]), "r"(b[0]), "r"(b[1]));
}

__device__ __forceinline__ uint32_t sm_u32(const void* p){
    uint32_t a;
    asm("{ .reg .u64 t; cvta.to.shared.u64 t, %1; cvt.u32.u64 %0, t; }"
        : "=r"(a) : "l"(p));
    return a;
}

__device__ __forceinline__ void cpasync16(uint32_t dst, const void* src){
    asm volatile("cp.async.cg.shared.global [%0], [%1], 16;"
                 :: "r"(dst), "l"(src) : "memory");
}
#define CP_COMMIT() asm volatile("cp.async.commit_group;" ::: "memory")
#define CP_WAIT1()  asm volatile("cp.async.wait_group 1;" ::: "memory")

// ---------------- kernel A: split X into limb planes (frag order) -----------
__global__ __launch_bounds__(256) void split_x_kernel(const float* __restrict__ X){
    const int id = blockIdx.x*256 + threadIdx.x;
    const int mb   = id >> 11;
    const int c    = (id >> 5) & 63;
    const int lane = id & 31;
    const int r0 = mb*16 + (lane >> 2);
    const int k0 = c*16 + 2*(lane & 3);
    const float* p0 = X + (size_t)r0*Dm + k0;
    float2 a00 = *reinterpret_cast<const float2*>(p0);
    float2 a10 = *reinterpret_cast<const float2*>(p0 + 8*Dm);
    float2 a01 = *reinterpret_cast<const float2*>(p0 + 8);
    float2 a11 = *reinterpret_cast<const float2*>(p0 + 8*Dm + 8);
    uint32_t h0,h1,h2,h3, l0,l1,l2,l3;
    h0 = packsplit(a00.x, a00.y, l0);
    h1 = packsplit(a10.x, a10.y, l1);
    h2 = packsplit(a01.x, a01.y, l2);
    h3 = packsplit(a11.x, a11.y, l3);
    *reinterpret_cast<uint4*>(&g_XS[(size_t)id*4])              = make_uint4(h0,h1,h2,h3);
    *reinterpret_cast<uint4*>(&g_XS[XS_CELLS*4 + (size_t)id*4]) = make_uint4(l0,l1,l2,l3);
}

// ---------------- kernel B: split W (x32) into limbs; also zero vsum ---------
__global__ __launch_bounds__(256) void split_w_kernel(
    const float* __restrict__ Wq, const float* __restrict__ Wk,
    const float* __restrict__ Wv)
{
    if (blockIdx.x < 16) g_vsum[blockIdx.x*256 + threadIdx.x] = 0.0f;

    const int id = blockIdx.x*256 + threadIdx.x;
    const int gemm = id >> 18;
    const int rem  = id & 262143;
    const int nb   = rem >> 11;
    const int c    = (rem >> 5) & 63;
    const int lane = rem & 31;
    const float* W = (gemm == 0) ? Wq : (gemm == 1) ? Wk : Wv;
    const int row = nb*8 + (lane >> 2);
    const int k0  = c*16 + 2*(lane & 3);
    const float* p = W + (size_t)row*Dm + k0;
    float2 b0 = *reinterpret_cast<const float2*>(p);
    float2 b1 = *reinterpret_cast<const float2*>(p + 8);
    uint32_t bh0, bh1, bl0, bl1;
    bh0 = packsplit(b0.x*32.f, b0.y*32.f, bl0);
    bh1 = packsplit(b1.x*32.f, b1.y*32.f, bl1);
    reinterpret_cast<uint4*>(&g_WS[(size_t)id*4])[0] = make_uint4(bh0,bh1,bl0,bl1);
}

// ======================= kernel 1: QKV GEMM ===================================
// Q,K: 3-limb split (mainloop A). V: 2-limb (mainloop B, separately compiled —
// V errors don't feed top-k; measured global rel_err ~2.1e-4 << 1e-3).
__global__ __launch_bounds__(256,2) void qkv_f16_kernel(
    const float* __restrict__ bq, const float* __restrict__ bk,
    const float* __restrict__ bv)
{
    const int gemm = blockIdx.z;
    const float* bias = (gemm == 0) ? bq : (gemm == 1) ? bk : bv;
    float* out = (gemm == 0) ? g_Q : (gemm == 1) ? g_K : g_V;

    const int n0 = blockIdx.x * 128;
    const int m0 = blockIdx.y * 128;

    extern __shared__ uint32_t smq[];
    const uint32_t smb = sm_u32(smq);

    const int t = threadIdx.x;
    const int lane = t & 31;
    const int wid  = t >> 5;
    const int warp_m = wid & 3;
    const int warp_n = wid >> 2;

    const int fA = wid, lA = lane;
    const char* srcAh = (const char*)g_XS
        + ((size_t)((blockIdx.y*8 + fA)*64)*32 + lA)*16;
    const char* srcAl = srcAh + XS_CELLS*16;
    const char* srcB1 = (const char*)g_WS
        + ((size_t)((gemm*128 + blockIdx.x*16 + fA)*64)*32 + lA)*16;
    const char* srcB2 = srcB1 + (size_t)8*64*32*16;
    const uint32_t dAh = (fA*32 + lA)*16;
    const uint32_t dAl = dAh + 4096;
    const uint32_t dB1 = 8192 + (fA*32 + lA)*16;
    const uint32_t dB2 = dB1 + 4096;

    float acc[2][8][4];
    #pragma unroll
    for (int i = 0; i < 2; ++i)
        #pragma unroll
        for (int j = 0; j < 8; ++j)
            #pragma unroll
            for (int r = 0; r < 4; ++r) acc[i][j][r] = 0.0f;

    #pragma unroll
    for (int p = 0; p < 2; ++p) {
        const uint32_t b = smb + p*16384;
        cpasync16(b + dAh, srcAh + (size_t)p*512);
        cpasync16(b + dAl, srcAl + (size_t)p*512);
        cpasync16(b + dB1, srcB1 + (size_t)p*512);
        cpasync16(b + dB2, srcB2 + (size_t)p*512);
        CP_COMMIT();
    }

    if (gemm != 2) {
        // ---- 3-limb mainloop (Q, K) — identical to R14 best ----
        #pragma unroll 1
        for (int c = 0; c < 64; ++c) {
            CP_WAIT1();
            __syncthreads();

            if (c + 2 < 64) {
                const uint32_t b = smb + ((c+2) & 3)*16384;
                cpasync16(b + dAh, srcAh + (size_t)(c+2)*512);
                cpasync16(b + dAl, srcAl + (size_t)(c+2)*512);
                cpasync16(b + dB1, srcB1 + (size_t)(c+2)*512);
                cpasync16(b + dB2, srcB2 + (size_t)(c+2)*512);
            }
            CP_COMMIT();

            const uint32_t* C = smq + (c & 3)*4096;
            uint32_t ah[2][4], al[2][4];
            #pragma unroll
            for (int im = 0; im < 2; ++im) {
                const int base = ((warp_m*2 + im)*32 + lane)*4;
                *reinterpret_cast<uint4*>(ah[im]) = *reinterpret_cast<const uint4*>(&C[base]);
                *reinterpret_cast<uint4*>(al[im]) = *reinterpret_cast<const uint4*>(&C[base + 1024]);
            }
            #pragma unroll
            for (int in = 0; in < 8; ++in) {
                const int base = 2048 + ((warp_n*8 + in)*32 + lane)*4;
                uint4 q = *reinterpret_cast<const uint4*>(&C[base]);
                uint32_t bh[2] = {q.x, q.y};
                uint32_t bl[2] = {q.z, q.w};
                #pragma unroll
                for (int im = 0; im < 2; ++im) {
                    mma16(acc[im][in], al[im], bh);
                    mma16(acc[im][in], ah[im], bl);
                    mma16(acc[im][in], ah[im], bh);
                }
            }
        }
    } else {
        // ---- 2-limb mainloop (V): drops alo.bhi ----
        #pragma unroll 1
        for (int c = 0; c < 64; ++c) {
            CP_WAIT1();
            __syncthreads();

            if (c + 2 < 64) {
                const uint32_t b = smb + ((c+2) & 3)*16384;
                cpasync16(b + dAh, srcAh + (size_t)(c+2)*512);
                cpasync16(b + dAl, srcAl + (size_t)(c+2)*512);
                cpasync16(b + dB1, srcB1 + (size_t)(c+2)*512);
                cpasync16(b + dB2, srcB2 + (size_t)(c+2)*512);
            }
            CP_COMMIT();

            const uint32_t* C = smq + (c & 3)*4096;
            uint32_t ah[2][4];
            #pragma unroll
            for (int im = 0; im < 2; ++im) {
                const int base = ((warp_m*2 + im)*32 + lane)*4;
                *reinterpret_cast<uint4*>(ah[im]) = *reinterpret_cast<const uint4*>(&C[base]);
            }
            #pragma unroll
            for (int in = 0; in < 8; ++in) {
                const int base = 2048 + ((warp_n*8 + in)*32 + lane)*4;
                uint4 q = *reinterpret_cast<const uint4*>(&C[base]);
                uint32_t bh[2] = {q.x, q.y};
                uint32_t bl[2] = {q.z, q.w};
                #pragma unroll
                for (int im = 0; im < 2; ++im) {
                    mma16(acc[im][in], ah[im], bl);
                    mma16(acc[im][in], ah[im], bh);
                }
            }
        }
    }

    const float inv32 = 0.03125f;
    #pragma unroll
    for (int im = 0; im < 2; ++im) {
        const int m = m0 + warp_m*32 + im*16 + (lane >> 2);
        #pragma unroll
        for (int in = 0; in < 8; ++in) {
            const int n = n0 + warp_n*64 + in*8 + (lane & 3)*2;
            const float b0 = __ldg(&bias[n]);
            const float b1 = __ldg(&bias[n+1]);
            float2 v0 = make_float2(acc[im][in][0]*inv32 + b0, acc[im][in][1]*inv32 + b1);
            float2 v1 = make_float2(acc[im][in][2]*inv32 + b0, acc[im][in][3]*inv32 + b1);
            *reinterpret_cast<float2*>(&out[(size_t)m*Dm + n])     = v0;
            *reinterpret_cast<float2*>(&out[(size_t)(m+8)*Dm + n]) = v1;
        }
    }
}

// ---------------- kernel 2: sparsity measure M via tensor cores --------------
__global__ __launch_bounds__(256) void m_tc_kernel(const int* __restrict__ idx_k){
    const int b = blockIdx.z, h = blockIdx.y;
    const int l0 = blockIdx.x * 128;

    __shared__ uint32_t Ah[8][4][32][4];
    __shared__ uint32_t Al[8][4][32][4];
    __shared__ uint32_t Bs[7][4][32][4];

    const int t = threadIdx.x;
    const int lane = t & 31;
    const int w = t >> 5;

    #pragma unroll
    for (int i = 0; i < 4; ++i) {
        const int id = t + i*256;
        const int frag = id >> 7, ln = (id >> 2) & 31, ch = id & 3;
        const int r0 = l0 + frag*16 + (ln >> 2);
        const int c0 = ch*16 + 2*(ln & 3);
        const float* q0 = &g_Q[(size_t)(b*Lv + r0)*Dm + h*DKv + c0];
        const float* q1 = q0 + 8*Dm;
        float2 x00 = *reinterpret_cast<const float2*>(q0);
        float2 x10 = *reinterpret_cast<const float2*>(q1);
        float2 x01 = *reinterpret_cast<const float2*>(q0 + 8);
        float2 x11 = *reinterpret_cast<const float2*>(q1 + 8);
        uint32_t h0,h1,h2,h3, e0,e1,e2,e3;
        h0 = packsplit(x00.x, x00.y, e0);
        h1 = packsplit(x10.x, x10.y, e1);
        h2 = packsplit(x01.x, x01.y, e2);
        h3 = packsplit(x11.x, x11.y, e3);
        *reinterpret_cast<uint4*>(&Ah[frag][ch][ln][0]) = make_uint4(h0,h1,h2,h3);
        *reinterpret_cast<uint4*>(&Al[frag][ch][ln][0]) = make_uint4(e0,e1,e2,e3);
    }
    #pragma unroll
    for (int i = 0; i < 4; ++i) {
        const int id = t + i*256;
        if (id < 896) {
            const int frag = id >> 7, ln = (id >> 2) & 31, ch = id & 3;
            const int n = frag*8 + (ln >> 2);
            uint32_t bh0=0, bh1=0, bl0=0, bl1=0;
            if (n < Uv) {
                const int row = __ldg(&idx_k[n]);
                const int c0 = ch*16 + 2*(ln & 3);
                const float* kp = &g_K[(size_t)(b*Lv + row)*Dm + h*DKv + c0];
                float2 y0 = *reinterpret_cast<const float2*>(kp);
                float2 y1 = *reinterpret_cast<const float2*>(kp + 8);
                bh0 = packsplit(y0.x, y0.y, bl0);
                bh1 = packsplit(y1.x, y1.y, bl1);
            }
            *reinterpret_cast<uint4*>(&Bs[frag][ch][ln][0]) = make_uint4(bh0,bh1,bl0,bl1);
        }
    }
    __syncthreads();

    float acc[7][4];
    #pragma unroll
    for (int in = 0; in < 7; ++in)
        #pragma unroll
        for (int r = 0; r < 4; ++r) acc[in][r] = 0.0f;

    #pragma unroll
    for (int ch = 0; ch < 4; ++ch) {
        uint32_t ahr[4], alr[4];
        *reinterpret_cast<uint4*>(ahr) = *reinterpret_cast<const uint4*>(&Ah[w][ch][lane][0]);
        *reinterpret_cast<uint4*>(alr) = *reinterpret_cast<const uint4*>(&Al[w][ch][lane][0]);
        #pragma unroll
        for (int in = 0; in < 7; ++in) {
            uint4 q = *reinterpret_cast<const uint4*>(&Bs[in][ch][lane][0]);
            uint32_t bh[2] = {q.x, q.y};
            uint32_t bl[2] = {q.z, q.w};
            mma16(acc[in], alr, bh);
            mma16(acc[in], ahr, bl);
            mma16(acc[in], ahr, bh);
        }
    }

    const int colbase = (lane & 3)*2;
    float mx0 = -1e30f, sm0 = 0.f, mx1 = -1e30f, sm1 = 0.f;
    #pragma unroll
    for (int in = 0; in < 7; ++in) {
        const int c0 = in*8 + colbase;
        if (c0 < Uv) {
            mx0 = fmaxf(mx0, acc[in][0]); sm0 += acc[in][0];
            mx1 = fmaxf(mx1, acc[in][2]); sm1 += acc[in][2];
        }
        if (c0 + 1 < Uv) {
            mx0 = fmaxf(mx0, acc[in][1]); sm0 += acc[in][1];
            mx1 = fmaxf(mx1, acc[in][3]); sm1 += acc[in][3];
        }
    }
    #pragma unroll
    for (int o = 1; o < 4; o <<= 1) {
        mx0 = fmaxf(mx0, __shfl_xor_sync(0xffffffffu, mx0, o));
        sm0 += __shfl_xor_sync(0xffffffffu, sm0, o);
        mx1 = fmaxf(mx1, __shfl_xor_sync(0xffffffffu, mx1, o));
        sm1 += __shfl_xor_sync(0xffffffffu, sm1, o);
    }
    if ((lane & 3) == 0) {
        const int r = l0 + w*16 + (lane >> 2);
        float* Mrow = &g_M[(size_t)(b*Hh + h)*Lv + r];
        Mrow[0] = mx0 - sm0*(1.0f/Uv);
        Mrow[8] = mx1 - sm1*(1.0f/Uv);
    }
}

// ---------------- kernel 3: top-k (k=50 of 8192) per (b,h) -------------------
__global__ __launch_bounds__(256) void topk_kernel(){
    const int bh = blockIdx.x;
    __shared__ float vals[Lv];
    __shared__ float rv[256];
    __shared__ int   ri[256];
    const int t = threadIdx.x;

    for (int i = t; i < Lv; i += 256) vals[i] = g_M[(size_t)bh*Lv + i];
    __syncthreads();

    for (int it = 0; it < Uv; ++it) {
        float best = -1e30f; int bi = Lv;
        for (int i = t; i < Lv; i += 256) {
            float v = vals[i];
            if (v > best || (v == best && i < bi)) { best = v; bi = i; }
        }
        rv[t] = best; ri[t] = bi;
        __syncthreads();
        for (int s = 128; s > 0; s >>= 1) {
            if (t < s) {
                if (rv[t+s] > rv[t] || (rv[t+s] == rv[t] && ri[t+s] < ri[t])) {
                    rv[t] = rv[t+s]; ri[t] = ri[t+s];
                }
            }
            __syncthreads();
        }
        if (t == 0) { g_top[bh*Uv + it] = ri[0]; vals[ri[0]] = -1e30f; }
        __syncthreads();
    }
}

// ---------------- kernel 4: V column sums (for mean) -------------------------
__global__ void vsum_kernel(){
    const int b = blockIdx.z;
    const int d = blockIdx.x*128 + threadIdx.x;
    const int c = blockIdx.y;
    float s = 0.0f;
    const int lbeg = c*256, lend = lbeg + 256;
    for (int l = lbeg; l < lend; ++l) s += g_V[(size_t)(b*Lv + l)*Dm + d];
    atomicAdd(&g_vsum[b*Dm + d], s);
}

// ---------------- kernel 5: flash attention (tensor-core QK^T and PV) --------
__global__ __launch_bounds__(512) void attn_partial_kernel(){
    extern __shared__ float sma[];
    const int bh = blockIdx.x;
    const int sp = blockIdx.y;
    const int b = bh / Hh, h = bh % Hh;
    const int t = threadIdx.x;
    const int lane = t & 31;
    const int w = t >> 5;

    float* Qraw = sma;
    float* Ps   = sma + 4096;
    float* m_s  = sma + 6400;
    float* l_s  = sma + 6464;
    float* c_s  = sma + 6528;
    uint32_t* Qh = reinterpret_cast<uint32_t*>(sma + 15296);
    uint32_t* Ql = Qh + 2048;
    uint32_t* Kl = Ql + 2048;
    uint32_t* Vl = Kl + 2048;
    const uint32_t smab = sm_u32(sma);

    for (int i = t; i < 64*64; i += 512) {
        const int q = i >> 6, d = i & 63;
        float v = 0.0f;
        if (q < Uv) {
            const int l = g_top[bh*Uv + q];
            v = g_Q[(size_t)(b*Lv + l)*Dm + h*DKv + d];
        }
        Qraw[i] = v;
    }
    if (t < Uv) { m_s[t] = -1e30f; l_s[t] = 0.0f; }
    if (t < 64) c_s[t] = 1.0f;
    __syncthreads();

    {
        const int mf = t >> 7, ch = (t >> 5) & 3, ln = t & 31;
        const int r0 = mf*16 + (ln >> 2), k0 = ch*16 + 2*(ln & 3);
        float2 x00 = *reinterpret_cast<const float2*>(&Qraw[r0*64 + k0]);
        float2 x10 = *reinterpret_cast<const float2*>(&Qraw[(r0+8)*64 + k0]);
        float2 x01 = *reinterpret_cast<const float2*>(&Qraw[r0*64 + k0 + 8]);
        float2 x11 = *reinterpret_cast<const float2*>(&Qraw[(r0+8)*64 + k0 + 8]);
        uint32_t h0,h1,h2,h3, e0,e1,e2,e3;
        h0 = packsplit(x00.x, x00.y, e0);
        h1 = packsplit(x10.x, x10.y, e1);
        h2 = packsplit(x01.x, x01.y, e2);
        h3 = packsplit(x11.x, x11.y, e3);
        const int cell = ((mf*4 + ch)*32 + ln)*4;
        *reinterpret_cast<uint4*>(&Qh[cell]) = make_uint4(h0,h1,h2,h3);
        *reinterpret_cast<uint4*>(&Ql[cell]) = make_uint4(e0,e1,e2,e3);
    }

    const int ldrow = t >> 4;
    const int lddq  = t & 15;
    const uint32_t kdst = smab + (6592 + ldrow*68 + lddq*4)*4;
    const uint32_t vdst = kdst + 2176*4;

    {
        size_t g = (size_t)(b*Lv + sp*LSPL + ldrow)*Dm + h*DKv + lddq*4;
        cpasync16(kdst, &g_K[g]);
        cpasync16(vdst, &g_V[g]);
    }
    CP_COMMIT();

    float o[2][4];
    #pragma unroll
    for (int j = 0; j < 2; ++j)
        #pragma unroll
        for (int r = 0; r < 4; ++r) o[j][r] = 0.0f;

    const int mf  = w >> 2;
    const int nfS = w & 3;
    const int nf0 = (w & 3)*2;

    const int NT = LSPL/TK;   // 32
    #pragma unroll 1
    for (int i = 0; i < NT; ++i) {
        __syncthreads();
        if (i + 1 < NT) {
            const uint32_t off = ((i+1) & 1)*4352*4;
            size_t g = (size_t)(b*Lv + sp*LSPL + (i+1)*TK + ldrow)*Dm + h*DKv + lddq*4;
            cpasync16(kdst + off, &g_K[g]);
            cpasync16(vdst + off, &g_V[g]);
        }
        CP_COMMIT();
        CP_WAIT1();
        __syncthreads();

        const float* Kr = sma + 6592 + (i & 1)*4352;
        const float* Vr = Kr + 2176;

        {
            const int nf = t >> 7, ch = (t >> 5) & 3, ln = t & 31;
            const int n = nf*8 + (ln >> 2), k0 = ch*16 + 2*(ln & 3);
            float2 y0 = *reinterpret_cast<const float2*>(&Kr[n*68 + k0]);
            float2 y1 = *reinterpret_cast<const float2*>(&Kr[n*68 + k0 + 8]);
            uint32_t bh0, bh1, bl0, bl1;
            bh0 = packsplit(y0.x, y0.y, bl0);
            bh1 = packsplit(y1.x, y1.y, bl1);
            *reinterpret_cast<uint4*>(&Kl[((nf*4+ch)*32+ln)*4]) = make_uint4(bh0,bh1,bl0,bl1);
        }
        {
            const int nf = t >> 6, ch = (t >> 5) & 1, ln = t & 31;
            const int n = nf*8 + (ln >> 2), k0 = ch*16 + 2*(ln & 3);
            float v00 = Vr[k0*68 + n],     v01 = Vr[(k0+1)*68 + n];
            float v10 = Vr[(k0+8)*68 + n], v11 = Vr[(k0+9)*68 + n];
            uint32_t bh0, bh1, bl0, bl1;
            bh0 = packsplit(v00, v01, bl0);
            bh1 = packsplit(v10, v11, bl1);
            *reinterpret_cast<uint4*>(&Vl[((nf*2+ch)*32+ln)*4]) = make_uint4(bh0,bh1,bl0,bl1);
        }
        __syncthreads();

        {
            float s[4] = {0.f, 0.f, 0.f, 0.f};
            #pragma unroll
            for (int ch = 0; ch < 4; ++ch) {
                uint32_t ah[4], al[4];
                *reinterpret_cast<uint4*>(ah) = *reinterpret_cast<const uint4*>(&Qh[((mf*4+ch)*32+lane)*4]);
                *reinterpret_cast<uint4*>(al) = *reinterpret_cast<const uint4*>(&Ql[((mf*4+ch)*32+lane)*4]);
                uint4 q4 = *reinterpret_cast<const uint4*>(&Kl[((nfS*4+ch)*32+lane)*4]);
                uint32_t bh2[2] = {q4.x, q4.y};
                uint32_t bl2[2] = {q4.z, q4.w};
                mma16(s, al, bh2);
                mma16(s, ah, bl2);
                mma16(s, ah, bh2);
            }
            const int q0 = mf*16 + (lane >> 2);
            const int col = nfS*8 + (lane & 3)*2;
            *reinterpret_cast<float2*>(&Ps[q0*36 + col])     = make_float2(s[0]*0.125f, s[1]*0.125f);
            *reinterpret_cast<float2*>(&Ps[(q0+8)*36 + col]) = make_float2(s[2]*0.125f, s[3]*0.125f);
        }
        __syncthreads();

        {
            const int q = (t < 400) ? (t >> 3) : 49;
            const int g = t & 7;
            float4 p4 = *reinterpret_cast<const float4*>(&Ps[q*36 + g*4]);
            float lm = fmaxf(fmaxf(p4.x, p4.y), fmaxf(p4.z, p4.w));
            #pragma unroll
            for (int oo = 1; oo < 8; oo <<= 1)
                lm = fmaxf(lm, __shfl_xor_sync(0xffffffffu, lm, oo, 8));
            const float mold = m_s[q];
            const float nm = fmaxf(mold, lm);
            p4.x = __expf(p4.x - nm);
            p4.y = __expf(p4.y - nm);
            p4.z = __expf(p4.z - nm);
            p4.w = __expf(p4.w - nm);
            float lsum = p4.x + p4.y + p4.z + p4.w;
            #pragma unroll
            for (int oo = 1; oo < 8; oo <<= 1)
                lsum += __shfl_xor_sync(0xffffffffu, lsum, oo, 8);
            if (t < 400) {
                *reinterpret_cast<float4*>(&Ps[q*36 + g*4]) = p4;
                if (g == 0) {
                    float cc = __expf(mold - nm);
                    c_s[q] = cc;
                    l_s[q] = l_s[q]*cc + lsum;
                    m_s[q] = nm;
                }
            }
        }
        __syncthreads();

        {
            const int ro = mf*16 + (lane >> 2);
            const float c0 = c_s[ro], c1 = c_s[ro + 8];
            #pragma unroll
            for (int j = 0; j < 2; ++j) {
                o[j][0] *= c0; o[j][1] *= c0;
                o[j][2] *= c1; o[j][3] *= c1;
            }
            #pragma unroll
            for (int ch = 0; ch < 2; ++ch) {
                const int k0 = ch*16 + 2*(lane & 3);
                float2 p00 = *reinterpret_cast<const float2*>(&Ps[ro*36 + k0]);
                float2 p10 = *reinterpret_cast<const float2*>(&Ps[(ro+8)*36 + k0]);
                float2 p01 = *reinterpret_cast<const float2*>(&Ps[ro*36 + k0 + 8]);
                float2 p11 = *reinterpret_cast<const float2*>(&Ps[(ro+8)*36 + k0 + 8]);
                uint32_t ah[4], al[4];
                ah[0] = packsplit(p00.x, p00.y, al[0]);
                ah[1] = packsplit(p10.x, p10.y, al[1]);
                ah[2] = packsplit(p01.x, p01.y, al[2]);
                ah[3] = packsplit(p11.x, p11.y, al[3]);
                #pragma unroll
                for (int j = 0; j < 2; ++j) {
                    uint4 q4 = *reinterpret_cast<const uint4*>(&Vl[(((nf0+j)*2+ch)*32+lane)*4]);
                    uint32_t bh2[2] = {q4.x, q4.y};
                    uint32_t bl2[2] = {q4.z, q4.w};
                    mma16(o[j], al, bh2);
                    mma16(o[j], ah, bl2);
                    mma16(o[j], ah, bh2);
                }
            }
        }
    }

    {
        const int ro = mf*16 + (lane >> 2);
        #pragma unroll
        for (int j = 0; j < 2; ++j) {
            const int d = (nf0+j)*8 + (lane & 3)*2;
            if (ro < Uv)
                *reinterpret_cast<float2*>(&g_pctx[(size_t)((bh*SPLIT+sp)*Uv + ro)*DKv + d])
                    = make_float2(o[j][0], o[j][1]);
            if (ro + 8 < Uv)
                *reinterpret_cast<float2*>(&g_pctx[(size_t)((bh*SPLIT+sp)*Uv + ro + 8)*DKv + d])
                    = make_float2(o[j][2], o[j][3]);
        }
    }
    if (t < Uv) {
        g_pm[(bh*SPLIT + sp)*Uv + t] = m_s[t];
        g_pl[(bh*SPLIT + sp)*Uv + t] = l_s[t];
    }
}

// ---------------- kernel 6: combine split partials ---------------------------
__global__ __launch_bounds__(64) void attn_combine_kernel(){
    const int i = blockIdx.x;
    const int q = i % Uv, bh = i / Uv;
    __shared__ float w[SPLIT];
    __shared__ float inv;
    if (threadIdx.x == 0) {
        float M = -1e30f;
        for (int s = 0; s < SPLIT; ++s) M = fmaxf(M, g_pm[(bh*SPLIT+s)*Uv + q]);
        float tot = 0.f;
        for (int s = 0; s < SPLIT; ++s) {
            float e = __expf(g_pm[(bh*SPLIT+s)*Uv + q] - M);
            w[s] = e;
            tot += g_pl[(bh*SPLIT+s)*Uv + q] * e;
        }
        inv = 1.0f / tot;
    }
    __syncthreads();
    const int d = threadIdx.x;
    float c = 0.f;
    for (int s = 0; s < SPLIT; ++s)
        c += g_pctx[(size_t)((bh*SPLIT+s)*Uv + q)*DKv + d] * w[s];
    g_ctx[(size_t)i*DKv + d] = c * inv;
}

// ---------------- kernel 7: base output row per batch ------------------------
__global__ __launch_bounds__(256) void base_kernel(const float* __restrict__ Wo,
                                                   const float* __restrict__ bo){
    const int b = blockIdx.y;
    const int warp = threadIdx.x >> 5, lane = threadIdx.x & 31;
    const int j = blockIdx.x*8 + warp;
    float s = 0.f;
    for (int d0 = lane; d0 < Dm; d0 += 32)
        s += g_vsum[b*Dm + d0] * Wo[(size_t)j*Dm + d0];
    #pragma unroll
    for (int o = 16; o; o >>= 1) s += __shfl_down_sync(0xffffffffu, s, o);
    if (lane == 0) g_base[b*Dm + j] = s*(1.0f/Lv) + bo[j];
}

// ---------------- kernel 8: broadcast base rows into output -------------------
__global__ void fill_kernel(float* __restrict__ out){
    const int i = blockIdx.x*blockDim.x + threadIdx.x;
    const int b  = i >> 21;
    const int j4 = i & 255;
    float4 v = *reinterpret_cast<const float4*>(&g_base[b*Dm + j4*4]);
    reinterpret_cast<float4*>(out)[i] = v;
}

// ---------------- kernel 9: rank-64 corrections (Wo read once per block) -----
__global__ __launch_bounds__(256) void corr_kernel(const float* __restrict__ Wo,
                                                   float* __restrict__ out){
    const int bh = blockIdx.y;
    const int b = bh / Hh, h = bh % Hh;
    const int j = blockIdx.x*256 + threadIdx.x;
    const int t = threadIdx.x;

    __shared__ float delta[Uv][DKv];
    __shared__ int   ls[Uv];

    if (t < Uv) ls[t] = g_top[bh*Uv + t];
    for (int i = t; i < Uv*DKv; i += 256) {
        const int u = i >> 6, dd = i & 63;
        delta[u][dd] = g_ctx[(size_t)(bh*Uv + u)*DKv + dd]
                     - g_vsum[b*Dm + h*DKv + dd]*(1.0f/Lv);
    }
    __syncthreads();

    float4 w[16];
    const float4* wr = reinterpret_cast<const float4*>(Wo + (size_t)j*Dm + h*DKv);
    #pragma unroll
    for (int dd = 0; dd < 16; ++dd) w[dd] = wr[dd];

    #pragma unroll 2
    for (int u = 0; u < Uv; ++u) {
        float s = 0.f;
        #pragma unroll
        for (int dd = 0; dd < 16; ++dd) {
            s += delta[u][dd*4+0]*w[dd].x + delta[u][dd*4+1]*w[dd].y
               + delta[u][dd*4+2]*w[dd].z + delta[u][dd*4+3]*w[dd].w;
        }
        atomicAdd(&out[(size_t)(b*Lv + ls[u])*Dm + j], s);
    }
}

// ---------------- launch ------------------------------------------------------
extern "C" void kernel_launch(void* const* d_in, const int* in_sizes, int n_in,
                              void* d_out, int out_size)
{
    const float* x    = (const float*)d_in[0];
    const float* Wq   = (const float*)d_in[1];
    const float* bq   = (const float*)d_in[2];
    const float* Wk   = (const float*)d_in[3];
    const float* bk   = (const float*)d_in[4];
    const float* Wv   = (const float*)d_in[5];
    const float* bv   = (const float*)d_in[6];
    const float* Wo   = (const float*)d_in[7];
    const float* bo   = (const float*)d_in[8];
    const int*   idxk = (const int*)d_in[9];
    float* out = (float*)d_out;

    cudaFuncSetAttribute(qkv_f16_kernel,
                         cudaFuncAttributeMaxDynamicSharedMemorySize, 65536);
    cudaFuncSetAttribute(attn_partial_kernel,
                         cudaFuncAttributeMaxDynamicSharedMemorySize, 94208);

    split_x_kernel<<<(2048*64*32)/256, 256>>>(x);
    split_w_kernel<<<(3*128*64*32)/256, 256>>>(Wq, Wk, Wv);
    qkv_f16_kernel<<<dim3(Dm/128, BLv/128, 3), 256, 65536>>>(bq, bk, bv);
    m_tc_kernel<<<dim3(Lv/128, Hh, Bv), 256>>>(idxk);
    vsum_kernel<<<dim3(Dm/128, Lv/256, Bv), 128>>>();
    topk_kernel<<<Bv*Hh, 256>>>();
    attn_partial_kernel<<<dim3(Bv*Hh, SPLIT), 512, 94208>>>();
    attn_combine_kernel<<<Bv*Hh*Uv, 64>>>();
    base_kernel<<<dim3(Dm/8, Bv), 256>>>(Wo, bo);
    fill_kernel<<<(BLv*Dm/4)/256, 256>>>(out);
    corr_kernel<<<dim3(4, Bv*Hh), 256>>>(Wo, out);
}